// round 15
// baseline (speedup 1.0000x reference)
#include <cuda_runtime.h>
#include <cstddef>

#define NN   128
#define PL   16384      // 128*128
#define VOL  2097152    // 128^3

typedef unsigned long long ull;

__device__ float g_A[8 * VOL];
__device__ float g_B[8 * VOL];
__device__ float g_C[8 * VOL];
__device__ float g_W[27 * VOL];
__device__ float g_f1[VOL];
__device__ float g_f2[VOL];
__device__ float g_tmp[8 * 27 * 28];          // reformatted conv weights staging

__constant__ __align__(16) float c_w[8 * 27 * 28];   // 24.2 KB, co-major

// ---- packed f32x2 helpers -------------------------------------------------
__device__ __forceinline__ ull f2pk(float lo, float hi) {
    ull r; asm("mov.b64 %0, {%1, %2};" : "=l"(r) : "f"(lo), "f"(hi)); return r;
}
__device__ __forceinline__ float2 f2un(ull v) {
    float2 r; asm("mov.b64 {%0, %1}, %2;" : "=f"(r.x), "=f"(r.y) : "l"(v)); return r;
}
__device__ __forceinline__ ull ffma2(ull a, ull b, ull c) {
    ull d; asm("fma.rn.f32x2 %0, %1, %2, %3;" : "=l"(d) : "l"(a), "l"(b), "l"(c)); return d;
}

// ---------------------------------------------------------------------------
// Weight reformat: [co][ci][tap] -> co-major [(ci*27+tap)*COP + co], zero-pad.
// ---------------------------------------------------------------------------
template<int CO>
__global__ void fmt_k(const float* __restrict__ wgt, float* __restrict__ dst)
{
    constexpr int COP = (CO + 1) & ~1;
    for (int i = threadIdx.x; i < 8 * 27 * COP; i += 256) {
        int co   = i % COP;
        int rest = i / COP;
        int ci   = rest / 27;
        int tap  = rest % 27;
        dst[i] = (co < CO) ? wgt[(co * 8 + ci) * 27 + tap] : 0.f;
    }
}

// ---------------------------------------------------------------------------
// 3x3x3 conv, C_in=8, C_out=CO, V=4 voxels/thread (98% of FFMA2 floor).
// Weights in the constant bank (broadcast port).
// ---------------------------------------------------------------------------
template<int CO, bool RELU, bool NORM, bool HB>
__global__ void __launch_bounds__(128, 3) conv_k(
    const float* __restrict__ in,
    const float* __restrict__ bias, float* __restrict__ out)
{
    constexpr int COP = (CO + 1) & ~1;   // 2, 8, 28
    constexpr int CP  = COP / 2;
    constexpr int V   = 4;

    int t  = blockIdx.x * 128 + threadIdx.x;   // [0, VOL/4)
    int w0 = (t & 31) << 2;
    int h  = (t >> 5) & 127;
    int d  = t >> 12;
    int pos = (d << 14) + (h << 7) + w0;

    ull acc[V][CP];
#pragma unroll
    for (int p = 0; p < CP; p++) {
        float blo = 0.f, bhi = 0.f;
        if (HB) {
            if (2 * p     < CO) blo = bias[2 * p];
            if (2 * p + 1 < CO) bhi = bias[2 * p + 1];
        }
        ull b = f2pk(blo, bhi);
#pragma unroll
        for (int v = 0; v < V; v++) acc[v][p] = b;
    }

    bool wl = (w0 > 0);
    bool wr = (w0 < 124);

#pragma unroll 1
    for (int ci = 0; ci < 8; ci++) {
        const float* cb  = in + ci * VOL + pos;
        const float* cwc = c_w + ci * 27 * COP;
#pragma unroll
        for (int dz = -1; dz <= 1; dz++) {
            bool zok = (unsigned)(d + dz) < 128u;
            float val[3][V + 2];
#pragma unroll
            for (int iy = 0; iy < 3; iy++) {
                bool ok = zok && ((unsigned)(h + iy - 1) < 128u);
                const float* r = cb + dz * PL + (iy - 1) * NN;
                float4 cv;
                if (ok) cv = *reinterpret_cast<const float4*>(r);
                else    { cv.x = 0.f; cv.y = 0.f; cv.z = 0.f; cv.w = 0.f; }
                val[iy][1] = cv.x; val[iy][2] = cv.y;
                val[iy][3] = cv.z; val[iy][4] = cv.w;
                val[iy][0] = (ok && wl) ? r[-1] : 0.f;
                val[iy][5] = (ok && wr) ? r[4]  : 0.f;
            }
#pragma unroll
            for (int iy = 0; iy < 3; iy++) {
                ull u[V + 2];
#pragma unroll
                for (int i = 0; i < V + 2; i++) u[i] = f2pk(val[iy][i], val[iy][i]);
                const float* sp = cwc + ((dz + 1) * 9 + iy * 3) * COP;
                if constexpr (CP % 2 == 0) {
#pragma unroll
                    for (int pp = 0; pp < CP; pp += 2) {
                        ulonglong2 wA = *reinterpret_cast<const ulonglong2*>(sp + 2 * pp);
                        ulonglong2 wB = *reinterpret_cast<const ulonglong2*>(sp + COP + 2 * pp);
                        ulonglong2 wC = *reinterpret_cast<const ulonglong2*>(sp + 2 * COP + 2 * pp);
#pragma unroll
                        for (int v = 0; v < V; v++) {
                            acc[v][pp]   = ffma2(u[v],     wA.x, acc[v][pp]);
                            acc[v][pp+1] = ffma2(u[v],     wA.y, acc[v][pp+1]);
                            acc[v][pp]   = ffma2(u[v + 1], wB.x, acc[v][pp]);
                            acc[v][pp+1] = ffma2(u[v + 1], wB.y, acc[v][pp+1]);
                            acc[v][pp]   = ffma2(u[v + 2], wC.x, acc[v][pp]);
                            acc[v][pp+1] = ffma2(u[v + 2], wC.y, acc[v][pp+1]);
                        }
                    }
                } else {
#pragma unroll
                    for (int p = 0; p < CP; p++) {
                        ull wA = *reinterpret_cast<const ull*>(sp + 2 * p);
                        ull wB = *reinterpret_cast<const ull*>(sp + COP + 2 * p);
                        ull wC = *reinterpret_cast<const ull*>(sp + 2 * COP + 2 * p);
#pragma unroll
                        for (int v = 0; v < V; v++) {
                            acc[v][p] = ffma2(u[v],     wA, acc[v][p]);
                            acc[v][p] = ffma2(u[v + 1], wB, acc[v][p]);
                            acc[v][p] = ffma2(u[v + 2], wC, acc[v][p]);
                        }
                    }
                }
            }
        }
    }

    float res[V][COP];
#pragma unroll
    for (int p = 0; p < CP; p++)
#pragma unroll
        for (int v = 0; v < V; v++) {
            float2 uu = f2un(acc[v][p]);
            res[v][2 * p] = uu.x; res[v][2 * p + 1] = uu.y;
        }

    if (NORM) {
#pragma unroll
        for (int v = 0; v < V; v++) {
            float s = 0.f;
#pragma unroll
            for (int c = 0; c < COP; c++) s += fabsf(res[v][c]);
            float inv = 1.f / fmaxf(s, 1e-12f);
#pragma unroll
            for (int c = 0; c < COP; c++) res[v][c] *= inv;
        }
    } else if (RELU) {
#pragma unroll
        for (int v = 0; v < V; v++)
#pragma unroll
            for (int c = 0; c < COP; c++) res[v][c] = fmaxf(res[v][c], 0.f);
    }

#pragma unroll
    for (int c = 0; c < CO; c++) {
        float4 st; st.x = res[0][c]; st.y = res[1][c]; st.z = res[2][c]; st.w = res[3][c];
        *reinterpret_cast<float4*>(out + c * VOL + pos) = st;
    }
}

// ---------------------------------------------------------------------------
// Adaptive conv over planes starting at z_base (count from grid size):
// out[c][v] = sum_tap in[c][v + off(tap)] * w[tap][v]
// R7-proven shape: 4 voxels/thread, channel-batched front loads.
// ---------------------------------------------------------------------------
template<int C>
__global__ void __launch_bounds__(128) adapt_k(
    const float* __restrict__ in, const float* __restrict__ wt,
    float* __restrict__ out, int z_base)
{
    constexpr int BC = (C < 4) ? C : 4;

    int t  = blockIdx.x * 128 + threadIdx.x;
    int w0 = (t & 31) << 2;
    int h  = (t >> 5) & 127;
    int d  = z_base + (t >> 12);
    int pos = (d << 14) + (h << 7) + w0;

    ull accA[C], accB[C];
#pragma unroll
    for (int c = 0; c < C; c++) { accA[c] = 0ull; accB[c] = 0ull; }

    bool wl = (w0 > 0);
    bool wr = (w0 < 124);

#pragma unroll
    for (int dz = -1; dz <= 1; dz++) {
        bool zok = (unsigned)(d + dz) < 128u;
#pragma unroll
        for (int dy = -1; dy <= 1; dy++) {
            bool ok = zok && ((unsigned)(h + dy) < 128u);
            int tap = (dz + 1) * 9 + (dy + 1) * 3;
            const float* wp = wt + tap * VOL + pos;
            ulonglong2 q0 = *reinterpret_cast<const ulonglong2*>(wp);            // dx=-1
            ulonglong2 q1 = *reinterpret_cast<const ulonglong2*>(wp + VOL);      // dx= 0
            ulonglong2 q2 = *reinterpret_cast<const ulonglong2*>(wp + 2 * VOL);  // dx=+1
            int off = dz * PL + dy * NN;
#pragma unroll
            for (int b = 0; b < C; b += BC) {
                float4 cv[BC]; float vl[BC], vr[BC];
#pragma unroll
                for (int u = 0; u < BC; u++) {
                    const float* r = in + (b + u) * VOL + pos + off;
                    if (ok) cv[u] = *reinterpret_cast<const float4*>(r);
                    else    { cv[u].x = 0.f; cv[u].y = 0.f; cv[u].z = 0.f; cv[u].w = 0.f; }
                    vl[u] = (ok && wl) ? r[-1] : 0.f;
                    vr[u] = (ok && wr) ? r[4]  : 0.f;
                }
#pragma unroll
                for (int u = 0; u < BC; u++) {
                    int c = b + u;
                    ull pm1  = f2pk(vl[u],   cv[u].x);
                    ull pmid = f2pk(cv[u].y, cv[u].z);
                    ull p01  = f2pk(cv[u].x, cv[u].y);
                    ull p23  = f2pk(cv[u].z, cv[u].w);
                    ull pp2  = f2pk(cv[u].w, vr[u]);
                    accA[c] = ffma2(pm1,  q0.x, accA[c]);
                    accB[c] = ffma2(pmid, q0.y, accB[c]);
                    accA[c] = ffma2(p01,  q1.x, accA[c]);
                    accB[c] = ffma2(p23,  q1.y, accB[c]);
                    accA[c] = ffma2(pmid, q2.x, accA[c]);
                    accB[c] = ffma2(pp2,  q2.y, accB[c]);
                }
            }
        }
    }
#pragma unroll
    for (int c = 0; c < C; c++) {
        float2 a = f2un(accA[c]);
        float2 b = f2un(accB[c]);
        float4 st; st.x = a.x; st.y = a.y; st.z = b.x; st.w = b.y;
        *reinterpret_cast<float4*>(out + c * VOL + pos) = st;
    }
}

// Helper: reformat weights and copy into the constant bank (graph-capturable).
template<int CO>
static void stage_weights(const float* wgt, float* tmp)
{
    constexpr int COP = (CO + 1) & ~1;
    fmt_k<CO><<<1, 256>>>(wgt, tmp);
    cudaMemcpyToSymbolAsync(c_w, tmp, 8 * 27 * COP * sizeof(float), 0,
                            cudaMemcpyDeviceToDevice, 0);
}

// z-chunked 3-pass adaptive chain: interleave passes in CH-plane chunks so
// the weight planes stay L2-resident across the three passes. CH chosen per
// channel count so chunk working set << 126 MB L2:
//   C=8: CH=16 -> ~46 MB;  C=1: CH=32 -> ~59 MB.
// Halo bookkeeping (p1 ends at e3+2, p2 at e3+1, p3 at e3) makes every
// in-place buffer-rotation hazard miss by >= 1 plane (R10/R14-validated).
template<int C, int CH>
static void adapt_chain(const float* in, const float* W,
                        float* t1, float* t2, float* out)
{
    dim3 bl(128);
    int s1 = 0, s2 = 0, s3 = 0;
    for (int e = CH; ; e += CH) {
        int e3 = (e   > 128) ? 128 : e;
        int e2 = (e3 + 1 > 128) ? 128 : e3 + 1;
        int e1 = (e3 + 2 > 128) ? 128 : e3 + 2;
        adapt_k<C><<<dim3((e1 - s1) * 32), bl>>>(in, W, t1, s1);
        adapt_k<C><<<dim3((e2 - s2) * 32), bl>>>(t1, W, t2, s2);
        adapt_k<C><<<dim3((e3 - s3) * 32), bl>>>(t2, W, out, s3);
        s1 = e1; s2 = e2; s3 = e3;
        if (e3 == 128) break;
    }
}

extern "C" void kernel_launch(void* const* d_in, const int* in_sizes, int n_in,
                              void* d_out, int out_size)
{
    const float* x    = (const float*)d_in[0];
    const float* a1w1 = (const float*)d_in[1];
    const float* a1b1 = (const float*)d_in[2];
    const float* a1w2 = (const float*)d_in[3];
    const float* a2w1 = (const float*)d_in[4];
    const float* a2b1 = (const float*)d_in[5];
    const float* a2w2 = (const float*)d_in[6];
    const float* a3w1 = (const float*)d_in[7];
    const float* a3b1 = (const float*)d_in[8];
    const float* a3w2 = (const float*)d_in[9];
    const float* midw = (const float*)d_in[10];
    const float* midb = (const float*)d_in[11];
    const float* outw = (const float*)d_in[12];
    const float* outb = (const float*)d_in[13];
    float* y = (float*)d_out;

    float *A, *B, *C, *W, *f1, *f2, *tmp;
    cudaGetSymbolAddress((void**)&A,   g_A);
    cudaGetSymbolAddress((void**)&B,   g_B);
    cudaGetSymbolAddress((void**)&C,   g_C);
    cudaGetSymbolAddress((void**)&W,   g_W);
    cudaGetSymbolAddress((void**)&f1,  g_f1);
    cudaGetSymbolAddress((void**)&f2,  g_f2);
    cudaGetSymbolAddress((void**)&tmp, g_tmp);

    dim3 bl(128);
    dim3 g4(VOL / 512);    // 4 voxels/thread, full volume

    // ---- block 1 (weights from x) : x -> A -> B -> A ----
    stage_weights<8>(a1w1, tmp);
    conv_k<8,  true,  false, true ><<<g4, bl>>>(x, a1b1, A);
    stage_weights<27>(a1w2, tmp);
    conv_k<27, false, true,  false><<<g4, bl>>>(A, nullptr, W);
    adapt_chain<8, 16>(x, W, A, B, A);            // block1 out -> A

    // ---- mid conv ----
    stage_weights<8>(midw, tmp);
    conv_k<8,  false, false, true ><<<g4, bl>>>(A, midb, B);   // mid -> B

    // ---- block 2 (weights from mid) : B -> A -> C -> A ----
    stage_weights<8>(a2w1, tmp);
    conv_k<8,  true,  false, true ><<<g4, bl>>>(B, a2b1, A);
    stage_weights<27>(a2w2, tmp);
    conv_k<27, false, true,  false><<<g4, bl>>>(A, nullptr, W);
    adapt_chain<8, 16>(B, W, A, C, A);            // block2 out (mid2) -> A

    // ---- out conv (8 -> 1) ----
    stage_weights<1>(outw, tmp);
    conv_k<1,  false, false, true ><<<g4, bl>>>(A, outb, f1);

    // ---- block 3 (weights from mid2 = A, applied to 1-channel final) ----
    stage_weights<8>(a3w1, tmp);
    conv_k<8,  true,  false, true ><<<g4, bl>>>(A, a3b1, B);
    stage_weights<27>(a3w2, tmp);
    conv_k<27, false, true,  false><<<g4, bl>>>(B, nullptr, W);
    adapt_chain<1, 32>(f1, W, f2, f1, y);         // R14-proven for 1 channel
}

// round 16
// speedup vs baseline: 1.0922x; 1.0922x over previous
#include <cuda_runtime.h>
#include <cstddef>

#define NN   128
#define PL   16384      // 128*128
#define VOL  2097152    // 128^3

typedef unsigned long long ull;

// small-bank layout (floats): 4x conv8 sets @1728 + 1x conv1 set @432
#define SM_A1W1 0
#define SM_A2W1 1728
#define SM_A3W1 3456
#define SM_MIDW 5184
#define SM_OUTW 6912
#define SM_TOTAL 7344
// big sets (conv27) staged in g_tmp at:
#define BIG0 7424
#define BIGSZ 6048      // 8*27*28

__device__ float g_A[8 * VOL];
__device__ float g_B[8 * VOL];
__device__ float g_C[8 * VOL];
__device__ float g_W[27 * VOL];
__device__ float g_f1[VOL];
__device__ float g_f2[VOL];
__device__ float g_tmp[BIG0 + 3 * BIGSZ];     // all reformatted weights

__constant__ __align__(16) float c_small[SM_TOTAL];  // 29.4 KB, permanent
__constant__ __align__(16) float c_big[BIGSZ];       // 24.2 KB, restaged 3x

// ---- packed f32x2 helpers -------------------------------------------------
__device__ __forceinline__ ull f2pk(float lo, float hi) {
    ull r; asm("mov.b64 %0, {%1, %2};" : "=l"(r) : "f"(lo), "f"(hi)); return r;
}
__device__ __forceinline__ float2 f2un(ull v) {
    float2 r; asm("mov.b64 {%0, %1}, %2;" : "=f"(r.x), "=f"(r.y) : "l"(v)); return r;
}
__device__ __forceinline__ ull ffma2(ull a, ull b, ull c) {
    ull d; asm("fma.rn.f32x2 %0, %1, %2, %3;" : "=l"(d) : "l"(a), "l"(b), "l"(c)); return d;
}

// ---------------------------------------------------------------------------
// Reformat ALL weight sets in one launch: [co][ci][tap] -> co-major
// [(ci*27+tap)*COP + co], zero-padded. One block per set.
// ---------------------------------------------------------------------------
__global__ void fmt_all_k(const float* __restrict__ a1w1, const float* __restrict__ a2w1,
                          const float* __restrict__ a3w1, const float* __restrict__ midw,
                          const float* __restrict__ outw, const float* __restrict__ a1w2,
                          const float* __restrict__ a2w2, const float* __restrict__ a3w2,
                          float* __restrict__ dst)
{
    const float* src; int CO, off;
    switch (blockIdx.x) {
        case 0: src = a1w1; CO = 8;  off = SM_A1W1; break;
        case 1: src = a2w1; CO = 8;  off = SM_A2W1; break;
        case 2: src = a3w1; CO = 8;  off = SM_A3W1; break;
        case 3: src = midw; CO = 8;  off = SM_MIDW; break;
        case 4: src = outw; CO = 1;  off = SM_OUTW; break;
        case 5: src = a1w2; CO = 27; off = BIG0;            break;
        case 6: src = a2w2; CO = 27; off = BIG0 + BIGSZ;    break;
        default: src = a3w2; CO = 27; off = BIG0 + 2 * BIGSZ; break;
    }
    int COP = (CO + 1) & ~1;
    int n = 8 * 27 * COP;
    for (int i = threadIdx.x; i < n; i += blockDim.x) {
        int co   = i % COP;
        int rest = i / COP;
        int ci   = rest / 27;
        int tap  = rest % 27;
        dst[off + i] = (co < CO) ? src[(co * 8 + ci) * 27 + tap] : 0.f;
    }
}

// ---------------------------------------------------------------------------
// 3x3x3 conv, C_in=8, C_out=CO, V=4 voxels/thread (98% of FFMA2 floor).
// Weights from the constant broadcast port: c_big for CO=27, c_small+OFF else.
// ---------------------------------------------------------------------------
template<int CO, int OFF, bool RELU, bool NORM, bool HB>
__global__ void __launch_bounds__(128, 3) conv_k(
    const float* __restrict__ in,
    const float* __restrict__ bias, float* __restrict__ out)
{
    constexpr int COP = (CO + 1) & ~1;   // 2, 8, 28
    constexpr int CP  = COP / 2;
    constexpr int V   = 4;

    int t  = blockIdx.x * 128 + threadIdx.x;   // [0, VOL/4)
    int w0 = (t & 31) << 2;
    int h  = (t >> 5) & 127;
    int d  = t >> 12;
    int pos = (d << 14) + (h << 7) + w0;

    ull acc[V][CP];
#pragma unroll
    for (int p = 0; p < CP; p++) {
        float blo = 0.f, bhi = 0.f;
        if (HB) {
            if (2 * p     < CO) blo = bias[2 * p];
            if (2 * p + 1 < CO) bhi = bias[2 * p + 1];
        }
        ull b = f2pk(blo, bhi);
#pragma unroll
        for (int v = 0; v < V; v++) acc[v][p] = b;
    }

    bool wl = (w0 > 0);
    bool wr = (w0 < 124);

#pragma unroll 1
    for (int ci = 0; ci < 8; ci++) {
        const float* cb  = in + ci * VOL + pos;
        const float* cwc = (CO == 27 ? c_big : c_small + OFF) + ci * 27 * COP;
#pragma unroll
        for (int dz = -1; dz <= 1; dz++) {
            bool zok = (unsigned)(d + dz) < 128u;
            float val[3][V + 2];
#pragma unroll
            for (int iy = 0; iy < 3; iy++) {
                bool ok = zok && ((unsigned)(h + iy - 1) < 128u);
                const float* r = cb + dz * PL + (iy - 1) * NN;
                float4 cv;
                if (ok) cv = *reinterpret_cast<const float4*>(r);
                else    { cv.x = 0.f; cv.y = 0.f; cv.z = 0.f; cv.w = 0.f; }
                val[iy][1] = cv.x; val[iy][2] = cv.y;
                val[iy][3] = cv.z; val[iy][4] = cv.w;
                val[iy][0] = (ok && wl) ? r[-1] : 0.f;
                val[iy][5] = (ok && wr) ? r[4]  : 0.f;
            }
#pragma unroll
            for (int iy = 0; iy < 3; iy++) {
                ull u[V + 2];
#pragma unroll
                for (int i = 0; i < V + 2; i++) u[i] = f2pk(val[iy][i], val[iy][i]);
                const float* sp = cwc + ((dz + 1) * 9 + iy * 3) * COP;
                if constexpr (CP % 2 == 0) {
#pragma unroll
                    for (int pp = 0; pp < CP; pp += 2) {
                        ulonglong2 wA = *reinterpret_cast<const ulonglong2*>(sp + 2 * pp);
                        ulonglong2 wB = *reinterpret_cast<const ulonglong2*>(sp + COP + 2 * pp);
                        ulonglong2 wC = *reinterpret_cast<const ulonglong2*>(sp + 2 * COP + 2 * pp);
#pragma unroll
                        for (int v = 0; v < V; v++) {
                            acc[v][pp]   = ffma2(u[v],     wA.x, acc[v][pp]);
                            acc[v][pp+1] = ffma2(u[v],     wA.y, acc[v][pp+1]);
                            acc[v][pp]   = ffma2(u[v + 1], wB.x, acc[v][pp]);
                            acc[v][pp+1] = ffma2(u[v + 1], wB.y, acc[v][pp+1]);
                            acc[v][pp]   = ffma2(u[v + 2], wC.x, acc[v][pp]);
                            acc[v][pp+1] = ffma2(u[v + 2], wC.y, acc[v][pp+1]);
                        }
                    }
                } else {
#pragma unroll
                    for (int p = 0; p < CP; p++) {
                        ull wA = *reinterpret_cast<const ull*>(sp + 2 * p);
                        ull wB = *reinterpret_cast<const ull*>(sp + COP + 2 * p);
                        ull wC = *reinterpret_cast<const ull*>(sp + 2 * COP + 2 * p);
#pragma unroll
                        for (int v = 0; v < V; v++) {
                            acc[v][p] = ffma2(u[v],     wA, acc[v][p]);
                            acc[v][p] = ffma2(u[v + 1], wB, acc[v][p]);
                            acc[v][p] = ffma2(u[v + 2], wC, acc[v][p]);
                        }
                    }
                }
            }
        }
    }

    float res[V][COP];
#pragma unroll
    for (int p = 0; p < CP; p++)
#pragma unroll
        for (int v = 0; v < V; v++) {
            float2 uu = f2un(acc[v][p]);
            res[v][2 * p] = uu.x; res[v][2 * p + 1] = uu.y;
        }

    if (NORM) {
#pragma unroll
        for (int v = 0; v < V; v++) {
            float s = 0.f;
#pragma unroll
            for (int c = 0; c < COP; c++) s += fabsf(res[v][c]);
            float inv = 1.f / fmaxf(s, 1e-12f);
#pragma unroll
            for (int c = 0; c < COP; c++) res[v][c] *= inv;
        }
    } else if (RELU) {
#pragma unroll
        for (int v = 0; v < V; v++)
#pragma unroll
            for (int c = 0; c < COP; c++) res[v][c] = fmaxf(res[v][c], 0.f);
    }

#pragma unroll
    for (int c = 0; c < CO; c++) {
        float4 st; st.x = res[0][c]; st.y = res[1][c]; st.z = res[2][c]; st.w = res[3][c];
        *reinterpret_cast<float4*>(out + c * VOL + pos) = st;
    }
}

// ---------------------------------------------------------------------------
// Adaptive conv over planes starting at z_base: R7-proven shape (4 voxels/
// thread, channel-batched front loads).
// ---------------------------------------------------------------------------
template<int C>
__global__ void __launch_bounds__(128) adapt_k(
    const float* __restrict__ in, const float* __restrict__ wt,
    float* __restrict__ out, int z_base)
{
    constexpr int BC = (C < 4) ? C : 4;

    int t  = blockIdx.x * 128 + threadIdx.x;
    int w0 = (t & 31) << 2;
    int h  = (t >> 5) & 127;
    int d  = z_base + (t >> 12);
    int pos = (d << 14) + (h << 7) + w0;

    ull accA[C], accB[C];
#pragma unroll
    for (int c = 0; c < C; c++) { accA[c] = 0ull; accB[c] = 0ull; }

    bool wl = (w0 > 0);
    bool wr = (w0 < 124);

#pragma unroll
    for (int dz = -1; dz <= 1; dz++) {
        bool zok = (unsigned)(d + dz) < 128u;
#pragma unroll
        for (int dy = -1; dy <= 1; dy++) {
            bool ok = zok && ((unsigned)(h + dy) < 128u);
            int tap = (dz + 1) * 9 + (dy + 1) * 3;
            const float* wp = wt + tap * VOL + pos;
            ulonglong2 q0 = *reinterpret_cast<const ulonglong2*>(wp);            // dx=-1
            ulonglong2 q1 = *reinterpret_cast<const ulonglong2*>(wp + VOL);      // dx= 0
            ulonglong2 q2 = *reinterpret_cast<const ulonglong2*>(wp + 2 * VOL);  // dx=+1
            int off = dz * PL + dy * NN;
#pragma unroll
            for (int b = 0; b < C; b += BC) {
                float4 cv[BC]; float vl[BC], vr[BC];
#pragma unroll
                for (int u = 0; u < BC; u++) {
                    const float* r = in + (b + u) * VOL + pos + off;
                    if (ok) cv[u] = *reinterpret_cast<const float4*>(r);
                    else    { cv[u].x = 0.f; cv[u].y = 0.f; cv[u].z = 0.f; cv[u].w = 0.f; }
                    vl[u] = (ok && wl) ? r[-1] : 0.f;
                    vr[u] = (ok && wr) ? r[4]  : 0.f;
                }
#pragma unroll
                for (int u = 0; u < BC; u++) {
                    int c = b + u;
                    ull pm1  = f2pk(vl[u],   cv[u].x);
                    ull pmid = f2pk(cv[u].y, cv[u].z);
                    ull p01  = f2pk(cv[u].x, cv[u].y);
                    ull p23  = f2pk(cv[u].z, cv[u].w);
                    ull pp2  = f2pk(cv[u].w, vr[u]);
                    accA[c] = ffma2(pm1,  q0.x, accA[c]);
                    accB[c] = ffma2(pmid, q0.y, accB[c]);
                    accA[c] = ffma2(p01,  q1.x, accA[c]);
                    accB[c] = ffma2(p23,  q1.y, accB[c]);
                    accA[c] = ffma2(pmid, q2.x, accA[c]);
                    accB[c] = ffma2(pp2,  q2.y, accB[c]);
                }
            }
        }
    }
#pragma unroll
    for (int c = 0; c < C; c++) {
        float2 a = f2un(accA[c]);
        float2 b = f2un(accB[c]);
        float4 st; st.x = a.x; st.y = a.y; st.z = b.x; st.w = b.y;
        *reinterpret_cast<float4*>(out + c * VOL + pos) = st;
    }
}

// z-chunked 3-pass adaptive chain for the 1-CHANNEL block only (R14-proven:
// ~59 MB chunk working set stays L2-resident; 8-channel chunking regresses).
static void adapt_chain1(const float* in, const float* W,
                         float* t1, float* t2, float* out)
{
    static const int e3[4] = {32, 64, 96, 128};
    static const int e2[4] = {33, 65, 97, 128};
    static const int e1[4] = {34, 66, 98, 128};
    dim3 bl(128);
    int s1 = 0, s2 = 0, s3 = 0;
    for (int i = 0; i < 4; i++) {
        adapt_k<1><<<dim3((e1[i] - s1) * 32), bl>>>(in, W, t1, s1);
        adapt_k<1><<<dim3((e2[i] - s2) * 32), bl>>>(t1, W, t2, s2);
        adapt_k<1><<<dim3((e3[i] - s3) * 32), bl>>>(t2, W, out, s3);
        s1 = e1[i]; s2 = e2[i]; s3 = e3[i];
    }
}

extern "C" void kernel_launch(void* const* d_in, const int* in_sizes, int n_in,
                              void* d_out, int out_size)
{
    const float* x    = (const float*)d_in[0];
    const float* a1w1 = (const float*)d_in[1];
    const float* a1b1 = (const float*)d_in[2];
    const float* a1w2 = (const float*)d_in[3];
    const float* a2w1 = (const float*)d_in[4];
    const float* a2b1 = (const float*)d_in[5];
    const float* a2w2 = (const float*)d_in[6];
    const float* a3w1 = (const float*)d_in[7];
    const float* a3b1 = (const float*)d_in[8];
    const float* a3w2 = (const float*)d_in[9];
    const float* midw = (const float*)d_in[10];
    const float* midb = (const float*)d_in[11];
    const float* outw = (const float*)d_in[12];
    const float* outb = (const float*)d_in[13];
    float* y = (float*)d_out;

    float *A, *B, *C, *W, *f1, *f2, *tmp;
    cudaGetSymbolAddress((void**)&A,   g_A);
    cudaGetSymbolAddress((void**)&B,   g_B);
    cudaGetSymbolAddress((void**)&C,   g_C);
    cudaGetSymbolAddress((void**)&W,   g_W);
    cudaGetSymbolAddress((void**)&f1,  g_f1);
    cudaGetSymbolAddress((void**)&f2,  g_f2);
    cudaGetSymbolAddress((void**)&tmp, g_tmp);

    dim3 bl(128);
    dim3 g4(VOL / 512);    // 4 voxels/thread, full volume

    // ---- stage ALL weights: 1 fmt kernel + 1 small-bank copy ----
    fmt_all_k<<<8, 256>>>(a1w1, a2w1, a3w1, midw, outw, a1w2, a2w2, a3w2, tmp);
    cudaMemcpyToSymbolAsync(c_small, tmp, SM_TOTAL * sizeof(float), 0,
                            cudaMemcpyDeviceToDevice, 0);

    // ---- block 1 (weights from x) : x -> A -> B -> A ----
    conv_k<8,  SM_A1W1, true,  false, true ><<<g4, bl>>>(x, a1b1, A);
    cudaMemcpyToSymbolAsync(c_big, tmp + BIG0, BIGSZ * sizeof(float), 0,
                            cudaMemcpyDeviceToDevice, 0);
    conv_k<27, 0, false, true,  false><<<g4, bl>>>(A, nullptr, W);
    adapt_k<8><<<g4, bl>>>(x, W, A, 0);
    adapt_k<8><<<g4, bl>>>(A, W, B, 0);
    adapt_k<8><<<g4, bl>>>(B, W, A, 0);           // block1 out -> A

    // ---- mid conv ----
    conv_k<8,  SM_MIDW, false, false, true ><<<g4, bl>>>(A, midb, B);   // mid -> B

    // ---- block 2 (weights from mid) : B -> A -> C -> A ----
    conv_k<8,  SM_A2W1, true,  false, true ><<<g4, bl>>>(B, a2b1, A);
    cudaMemcpyToSymbolAsync(c_big, tmp + BIG0 + BIGSZ, BIGSZ * sizeof(float), 0,
                            cudaMemcpyDeviceToDevice, 0);
    conv_k<27, 0, false, true,  false><<<g4, bl>>>(A, nullptr, W);
    adapt_k<8><<<g4, bl>>>(B, W, A, 0);
    adapt_k<8><<<g4, bl>>>(A, W, C, 0);
    adapt_k<8><<<g4, bl>>>(C, W, A, 0);           // block2 out (mid2) -> A

    // ---- out conv (8 -> 1) ----
    conv_k<1,  SM_OUTW, false, false, true ><<<g4, bl>>>(A, outb, f1);

    // ---- block 3 (weights from mid2 = A, applied to 1-channel final) ----
    conv_k<8,  SM_A3W1, true,  false, true ><<<g4, bl>>>(A, a3b1, B);
    cudaMemcpyToSymbolAsync(c_big, tmp + BIG0 + 2 * BIGSZ, BIGSZ * sizeof(float), 0,
                            cudaMemcpyDeviceToDevice, 0);
    conv_k<27, 0, false, true,  false><<<g4, bl>>>(B, nullptr, W);
    adapt_chain1(f1, W, f2, f1, y);               // z-chunked (R14-proven)
}

// round 17
// speedup vs baseline: 1.0973x; 1.0047x over previous
#include <cuda_runtime.h>
#include <cstddef>

#define NN   128
#define PL   16384      // 128*128
#define VOL  2097152    // 128^3

typedef unsigned long long ull;

// small-bank layout (floats): 4x conv8 sets @1728 + 1x conv1 set @432
#define SM_A1W1 0
#define SM_A2W1 1728
#define SM_A3W1 3456
#define SM_MIDW 5184
#define SM_OUTW 6912
#define SM_TOTAL 7344
// big sets (conv27) staged in g_tmp at:
#define BIG0 7424
#define BIGSZ 6048      // 8*27*28

__device__ float g_A[8 * VOL];
__device__ float g_B[8 * VOL];
__device__ float g_C[8 * VOL];
__device__ float g_W[27 * VOL];
__device__ float g_f1[VOL];
__device__ float g_f2[VOL];
__device__ float g_tmp[BIG0 + 3 * BIGSZ];     // all reformatted weights

__constant__ __align__(16) float c_small[SM_TOTAL];  // 29.4 KB, permanent
__constant__ __align__(16) float c_big[BIGSZ];       // 24.2 KB, restaged 3x

// ---- packed f32x2 helpers -------------------------------------------------
__device__ __forceinline__ ull f2pk(float lo, float hi) {
    ull r; asm("mov.b64 %0, {%1, %2};" : "=l"(r) : "f"(lo), "f"(hi)); return r;
}
__device__ __forceinline__ float2 f2un(ull v) {
    float2 r; asm("mov.b64 {%0, %1}, %2;" : "=f"(r.x), "=f"(r.y) : "l"(v)); return r;
}
__device__ __forceinline__ ull ffma2(ull a, ull b, ull c) {
    ull d; asm("fma.rn.f32x2 %0, %1, %2, %3;" : "=l"(d) : "l"(a), "l"(b), "l"(c)); return d;
}

// ---------------------------------------------------------------------------
// Reformat ALL weight sets in one launch: [co][ci][tap] -> co-major
// [(ci*27+tap)*COP + co], zero-padded. One block per set.
// ---------------------------------------------------------------------------
__global__ void fmt_all_k(const float* __restrict__ a1w1, const float* __restrict__ a2w1,
                          const float* __restrict__ a3w1, const float* __restrict__ midw,
                          const float* __restrict__ outw, const float* __restrict__ a1w2,
                          const float* __restrict__ a2w2, const float* __restrict__ a3w2,
                          float* __restrict__ dst)
{
    const float* src; int CO, off;
    switch (blockIdx.x) {
        case 0: src = a1w1; CO = 8;  off = SM_A1W1; break;
        case 1: src = a2w1; CO = 8;  off = SM_A2W1; break;
        case 2: src = a3w1; CO = 8;  off = SM_A3W1; break;
        case 3: src = midw; CO = 8;  off = SM_MIDW; break;
        case 4: src = outw; CO = 1;  off = SM_OUTW; break;
        case 5: src = a1w2; CO = 27; off = BIG0;            break;
        case 6: src = a2w2; CO = 27; off = BIG0 + BIGSZ;    break;
        default: src = a3w2; CO = 27; off = BIG0 + 2 * BIGSZ; break;
    }
    int COP = (CO + 1) & ~1;
    int n = 8 * 27 * COP;
    for (int i = threadIdx.x; i < n; i += blockDim.x) {
        int co   = i % COP;
        int rest = i / COP;
        int ci   = rest / 27;
        int tap  = rest % 27;
        dst[off + i] = (co < CO) ? src[(co * 8 + ci) * 27 + tap] : 0.f;
    }
}

// ---------------------------------------------------------------------------
// 3x3x3 conv, C_in=8, C_out=CO, V=4 voxels/thread (98% of FFMA2 floor).
// Weights from the constant broadcast port: c_big for CO=27, c_small+OFF else.
// ---------------------------------------------------------------------------
template<int CO, int OFF, bool RELU, bool NORM, bool HB>
__global__ void __launch_bounds__(128, 3) conv_k(
    const float* __restrict__ in,
    const float* __restrict__ bias, float* __restrict__ out)
{
    constexpr int COP = (CO + 1) & ~1;   // 2, 8, 28
    constexpr int CP  = COP / 2;
    constexpr int V   = 4;

    int t  = blockIdx.x * 128 + threadIdx.x;   // [0, VOL/4)
    int w0 = (t & 31) << 2;
    int h  = (t >> 5) & 127;
    int d  = t >> 12;
    int pos = (d << 14) + (h << 7) + w0;

    ull acc[V][CP];
#pragma unroll
    for (int p = 0; p < CP; p++) {
        float blo = 0.f, bhi = 0.f;
        if (HB) {
            if (2 * p     < CO) blo = bias[2 * p];
            if (2 * p + 1 < CO) bhi = bias[2 * p + 1];
        }
        ull b = f2pk(blo, bhi);
#pragma unroll
        for (int v = 0; v < V; v++) acc[v][p] = b;
    }

    bool wl = (w0 > 0);
    bool wr = (w0 < 124);

#pragma unroll 1
    for (int ci = 0; ci < 8; ci++) {
        const float* cb  = in + ci * VOL + pos;
        const float* cwc = (CO == 27 ? c_big : c_small + OFF) + ci * 27 * COP;
#pragma unroll
        for (int dz = -1; dz <= 1; dz++) {
            bool zok = (unsigned)(d + dz) < 128u;
            float val[3][V + 2];
#pragma unroll
            for (int iy = 0; iy < 3; iy++) {
                bool ok = zok && ((unsigned)(h + iy - 1) < 128u);
                const float* r = cb + dz * PL + (iy - 1) * NN;
                float4 cv;
                if (ok) cv = *reinterpret_cast<const float4*>(r);
                else    { cv.x = 0.f; cv.y = 0.f; cv.z = 0.f; cv.w = 0.f; }
                val[iy][1] = cv.x; val[iy][2] = cv.y;
                val[iy][3] = cv.z; val[iy][4] = cv.w;
                val[iy][0] = (ok && wl) ? r[-1] : 0.f;
                val[iy][5] = (ok && wr) ? r[4]  : 0.f;
            }
#pragma unroll
            for (int iy = 0; iy < 3; iy++) {
                ull u[V + 2];
#pragma unroll
                for (int i = 0; i < V + 2; i++) u[i] = f2pk(val[iy][i], val[iy][i]);
                const float* sp = cwc + ((dz + 1) * 9 + iy * 3) * COP;
                if constexpr (CP % 2 == 0) {
#pragma unroll
                    for (int pp = 0; pp < CP; pp += 2) {
                        ulonglong2 wA = *reinterpret_cast<const ulonglong2*>(sp + 2 * pp);
                        ulonglong2 wB = *reinterpret_cast<const ulonglong2*>(sp + COP + 2 * pp);
                        ulonglong2 wC = *reinterpret_cast<const ulonglong2*>(sp + 2 * COP + 2 * pp);
#pragma unroll
                        for (int v = 0; v < V; v++) {
                            acc[v][pp]   = ffma2(u[v],     wA.x, acc[v][pp]);
                            acc[v][pp+1] = ffma2(u[v],     wA.y, acc[v][pp+1]);
                            acc[v][pp]   = ffma2(u[v + 1], wB.x, acc[v][pp]);
                            acc[v][pp+1] = ffma2(u[v + 1], wB.y, acc[v][pp+1]);
                            acc[v][pp]   = ffma2(u[v + 2], wC.x, acc[v][pp]);
                            acc[v][pp+1] = ffma2(u[v + 2], wC.y, acc[v][pp+1]);
                        }
                    }
                } else {
#pragma unroll
                    for (int p = 0; p < CP; p++) {
                        ull wA = *reinterpret_cast<const ull*>(sp + 2 * p);
                        ull wB = *reinterpret_cast<const ull*>(sp + COP + 2 * p);
                        ull wC = *reinterpret_cast<const ull*>(sp + 2 * COP + 2 * p);
#pragma unroll
                        for (int v = 0; v < V; v++) {
                            acc[v][p] = ffma2(u[v],     wA, acc[v][p]);
                            acc[v][p] = ffma2(u[v + 1], wB, acc[v][p]);
                            acc[v][p] = ffma2(u[v + 2], wC, acc[v][p]);
                        }
                    }
                }
            }
        }
    }

    float res[V][COP];
#pragma unroll
    for (int p = 0; p < CP; p++)
#pragma unroll
        for (int v = 0; v < V; v++) {
            float2 uu = f2un(acc[v][p]);
            res[v][2 * p] = uu.x; res[v][2 * p + 1] = uu.y;
        }

    if (NORM) {
#pragma unroll
        for (int v = 0; v < V; v++) {
            float s = 0.f;
#pragma unroll
            for (int c = 0; c < COP; c++) s += fabsf(res[v][c]);
            float inv = 1.f / fmaxf(s, 1e-12f);
#pragma unroll
            for (int c = 0; c < COP; c++) res[v][c] *= inv;
        }
    } else if (RELU) {
#pragma unroll
        for (int v = 0; v < V; v++)
#pragma unroll
            for (int c = 0; c < COP; c++) res[v][c] = fmaxf(res[v][c], 0.f);
    }

#pragma unroll
    for (int c = 0; c < CO; c++) {
        float4 st; st.x = res[0][c]; st.y = res[1][c]; st.z = res[2][c]; st.w = res[3][c];
        *reinterpret_cast<float4*>(out + c * VOL + pos) = st;
    }
}

// ---------------------------------------------------------------------------
// Adaptive conv over planes starting at z_base. 4 voxels/thread; ALL C
// channels front-batched per (dz,dy) tap row for maximum MLP (BC = C).
// ---------------------------------------------------------------------------
template<int C>
__global__ void __launch_bounds__(128) adapt_k(
    const float* __restrict__ in, const float* __restrict__ wt,
    float* __restrict__ out, int z_base)
{
    constexpr int BC = C;   // full-channel batch: 3*C LDGs in flight per row

    int t  = blockIdx.x * 128 + threadIdx.x;
    int w0 = (t & 31) << 2;
    int h  = (t >> 5) & 127;
    int d  = z_base + (t >> 12);
    int pos = (d << 14) + (h << 7) + w0;

    ull accA[C], accB[C];
#pragma unroll
    for (int c = 0; c < C; c++) { accA[c] = 0ull; accB[c] = 0ull; }

    bool wl = (w0 > 0);
    bool wr = (w0 < 124);

#pragma unroll
    for (int dz = -1; dz <= 1; dz++) {
        bool zok = (unsigned)(d + dz) < 128u;
#pragma unroll
        for (int dy = -1; dy <= 1; dy++) {
            bool ok = zok && ((unsigned)(h + dy) < 128u);
            int tap = (dz + 1) * 9 + (dy + 1) * 3;
            const float* wp = wt + tap * VOL + pos;
            ulonglong2 q0 = *reinterpret_cast<const ulonglong2*>(wp);            // dx=-1
            ulonglong2 q1 = *reinterpret_cast<const ulonglong2*>(wp + VOL);      // dx= 0
            ulonglong2 q2 = *reinterpret_cast<const ulonglong2*>(wp + 2 * VOL);  // dx=+1
            int off = dz * PL + dy * NN;
#pragma unroll
            for (int b = 0; b < C; b += BC) {
                float4 cv[BC]; float vl[BC], vr[BC];
#pragma unroll
                for (int u = 0; u < BC; u++) {
                    const float* r = in + (b + u) * VOL + pos + off;
                    if (ok) cv[u] = *reinterpret_cast<const float4*>(r);
                    else    { cv[u].x = 0.f; cv[u].y = 0.f; cv[u].z = 0.f; cv[u].w = 0.f; }
                    vl[u] = (ok && wl) ? r[-1] : 0.f;
                    vr[u] = (ok && wr) ? r[4]  : 0.f;
                }
#pragma unroll
                for (int u = 0; u < BC; u++) {
                    int c = b + u;
                    ull pm1  = f2pk(vl[u],   cv[u].x);
                    ull pmid = f2pk(cv[u].y, cv[u].z);
                    ull p01  = f2pk(cv[u].x, cv[u].y);
                    ull p23  = f2pk(cv[u].z, cv[u].w);
                    ull pp2  = f2pk(cv[u].w, vr[u]);
                    accA[c] = ffma2(pm1,  q0.x, accA[c]);
                    accB[c] = ffma2(pmid, q0.y, accB[c]);
                    accA[c] = ffma2(p01,  q1.x, accA[c]);
                    accB[c] = ffma2(p23,  q1.y, accB[c]);
                    accA[c] = ffma2(pmid, q2.x, accA[c]);
                    accB[c] = ffma2(pp2,  q2.y, accB[c]);
                }
            }
        }
    }
#pragma unroll
    for (int c = 0; c < C; c++) {
        float2 a = f2un(accA[c]);
        float2 b = f2un(accB[c]);
        float4 st; st.x = a.x; st.y = a.y; st.z = b.x; st.w = b.y;
        *reinterpret_cast<float4*>(out + c * VOL + pos) = st;
    }
}

// z-chunked 3-pass adaptive chain for the 1-CHANNEL block only (R14-proven).
static void adapt_chain1(const float* in, const float* W,
                         float* t1, float* t2, float* out)
{
    static const int e3[4] = {32, 64, 96, 128};
    static const int e2[4] = {33, 65, 97, 128};
    static const int e1[4] = {34, 66, 98, 128};
    dim3 bl(128);
    int s1 = 0, s2 = 0, s3 = 0;
    for (int i = 0; i < 4; i++) {
        adapt_k<1><<<dim3((e1[i] - s1) * 32), bl>>>(in, W, t1, s1);
        adapt_k<1><<<dim3((e2[i] - s2) * 32), bl>>>(t1, W, t2, s2);
        adapt_k<1><<<dim3((e3[i] - s3) * 32), bl>>>(t2, W, out, s3);
        s1 = e1[i]; s2 = e2[i]; s3 = e3[i];
    }
}

extern "C" void kernel_launch(void* const* d_in, const int* in_sizes, int n_in,
                              void* d_out, int out_size)
{
    const float* x    = (const float*)d_in[0];
    const float* a1w1 = (const float*)d_in[1];
    const float* a1b1 = (const float*)d_in[2];
    const float* a1w2 = (const float*)d_in[3];
    const float* a2w1 = (const float*)d_in[4];
    const float* a2b1 = (const float*)d_in[5];
    const float* a2w2 = (const float*)d_in[6];
    const float* a3w1 = (const float*)d_in[7];
    const float* a3b1 = (const float*)d_in[8];
    const float* a3w2 = (const float*)d_in[9];
    const float* midw = (const float*)d_in[10];
    const float* midb = (const float*)d_in[11];
    const float* outw = (const float*)d_in[12];
    const float* outb = (const float*)d_in[13];
    float* y = (float*)d_out;

    float *A, *B, *C, *W, *f1, *f2, *tmp;
    cudaGetSymbolAddress((void**)&A,   g_A);
    cudaGetSymbolAddress((void**)&B,   g_B);
    cudaGetSymbolAddress((void**)&C,   g_C);
    cudaGetSymbolAddress((void**)&W,   g_W);
    cudaGetSymbolAddress((void**)&f1,  g_f1);
    cudaGetSymbolAddress((void**)&f2,  g_f2);
    cudaGetSymbolAddress((void**)&tmp, g_tmp);

    dim3 bl(128);
    dim3 g4(VOL / 512);    // 4 voxels/thread, full volume

    // ---- stage ALL weights: 1 fmt kernel + 1 small-bank copy ----
    fmt_all_k<<<8, 256>>>(a1w1, a2w1, a3w1, midw, outw, a1w2, a2w2, a3w2, tmp);
    cudaMemcpyToSymbolAsync(c_small, tmp, SM_TOTAL * sizeof(float), 0,
                            cudaMemcpyDeviceToDevice, 0);

    // ---- block 1 (weights from x) : x -> A -> B -> A ----
    conv_k<8,  SM_A1W1, true,  false, true ><<<g4, bl>>>(x, a1b1, A);
    cudaMemcpyToSymbolAsync(c_big, tmp + BIG0, BIGSZ * sizeof(float), 0,
                            cudaMemcpyDeviceToDevice, 0);
    conv_k<27, 0, false, true,  false><<<g4, bl>>>(A, nullptr, W);
    adapt_k<8><<<g4, bl>>>(x, W, A, 0);
    adapt_k<8><<<g4, bl>>>(A, W, B, 0);
    adapt_k<8><<<g4, bl>>>(B, W, A, 0);           // block1 out -> A

    // ---- mid conv ----
    conv_k<8,  SM_MIDW, false, false, true ><<<g4, bl>>>(A, midb, B);   // mid -> B

    // ---- block 2 (weights from mid) : B -> A -> C -> A ----
    conv_k<8,  SM_A2W1, true,  false, true ><<<g4, bl>>>(B, a2b1, A);
    cudaMemcpyToSymbolAsync(c_big, tmp + BIG0 + BIGSZ, BIGSZ * sizeof(float), 0,
                            cudaMemcpyDeviceToDevice, 0);
    conv_k<27, 0, false, true,  false><<<g4, bl>>>(A, nullptr, W);
    adapt_k<8><<<g4, bl>>>(B, W, A, 0);
    adapt_k<8><<<g4, bl>>>(A, W, C, 0);
    adapt_k<8><<<g4, bl>>>(C, W, A, 0);           // block2 out (mid2) -> A

    // ---- out conv (8 -> 1) ----
    conv_k<1,  SM_OUTW, false, false, true ><<<g4, bl>>>(A, outb, f1);

    // ---- block 3 (weights from mid2 = A, applied to 1-channel final) ----
    conv_k<8,  SM_A3W1, true,  false, true ><<<g4, bl>>>(A, a3b1, B);
    cudaMemcpyToSymbolAsync(c_big, tmp + BIG0 + 2 * BIGSZ, BIGSZ * sizeof(float), 0,
                            cudaMemcpyDeviceToDevice, 0);
    conv_k<27, 0, false, true,  false><<<g4, bl>>>(B, nullptr, W);
    adapt_chain1(f1, W, f2, f1, y);               // z-chunked (R14-proven)
}